// round 7
// baseline (speedup 1.0000x reference)
#include <cuda_runtime.h>
#include <cuda_fp16.h>
#include <cstdint>

#define TOKS 16384
#define HDIM 1024
#define IDIM 2048
#define NE   8
#define STG  3
#define STAGE_BYTES 49152           // A: 8 chunks x 256 rows x 16B = 32KB, B: 8 x 128 x 16B = 16KB
#define SMEM_BYTES  (STG * STAGE_BYTES)

// ---------------- static scratch ----------------
__device__ int   g_cnt[16];
__device__ int   g_off[16];
__device__ int   g_tok[NE * TOKS];
__device__ float g_wt [NE * TOKS];
__device__ __align__(256) __half g_xh[(size_t)TOKS * HDIM];
__device__ __align__(256) __half g_Wgh[(size_t)(NE + 1) * IDIM * HDIM];  // slot NE = shared
__device__ __align__(256) __half g_Wuh[(size_t)(NE + 1) * IDIM * HDIM];
__device__ __align__(256) __half g_Wdh[(size_t)(NE + 1) * HDIM * IDIM];
__device__ __align__(256) __half g_hh[(size_t)3 * TOKS * IDIM];  // routed packed, shared at 2*TOKS

// ---------------- helpers ----------------
__device__ __forceinline__ uint32_t smem_u32(const void* p) {
    uint32_t a;
    asm("{ .reg .u64 t; cvta.to.shared.u64 t, %1; cvt.u32.u64 %0, t; }" : "=r"(a) : "l"(p));
    return a;
}
__device__ __forceinline__ void cp16(uint32_t dst, const __half* src, int sz) {
    asm volatile("cp.async.cg.shared.global [%0], [%1], 16, %2;"
                 :: "r"(dst), "l"(src), "r"(sz) : "memory");
}
__device__ __forceinline__ void cp_commit() { asm volatile("cp.async.commit_group;" ::: "memory"); }
__device__ __forceinline__ void cp_wait()   { asm volatile("cp.async.wait_group %0;" :: "n"(STG - 2) : "memory"); }

__device__ __forceinline__ void ldsm4(uint32_t* r, uint32_t addr) {
    asm volatile("ldmatrix.sync.aligned.m8n8.x4.shared.b16 {%0,%1,%2,%3}, [%4];"
                 : "=r"(r[0]), "=r"(r[1]), "=r"(r[2]), "=r"(r[3]) : "r"(addr));
}
__device__ __forceinline__ void mma_f16(float* c, const uint32_t* a, uint32_t b0, uint32_t b1) {
    asm volatile(
        "mma.sync.aligned.m16n8k16.row.col.f32.f16.f16.f32 "
        "{%0,%1,%2,%3}, {%4,%5,%6,%7}, {%8,%9}, {%0,%1,%2,%3};\n"
        : "+f"(c[0]), "+f"(c[1]), "+f"(c[2]), "+f"(c[3])
        : "r"(a[0]), "r"(a[1]), "r"(a[2]), "r"(a[3]), "r"(b0), "r"(b1));
}

// ---------------- kernel: zero counters ----------------
__global__ void zero_cnt_kernel() {
    if (threadIdx.x < 16) g_cnt[threadIdx.x] = 0;
}

// ---------------- kernel: fp32 -> fp16 x convert ----------------
__global__ void cvt_x_kernel(const float* __restrict__ src) {
    size_t i = ((size_t)blockIdx.x * 256 + threadIdx.x) * 8;
    float4 v0 = *(const float4*)(src + i);
    float4 v1 = *(const float4*)(src + i + 4);
    __half2 h[4];
    h[0] = __floats2half2_rn(v0.x, v0.y);
    h[1] = __floats2half2_rn(v0.z, v0.w);
    h[2] = __floats2half2_rn(v1.x, v1.y);
    h[3] = __floats2half2_rn(v1.z, v1.w);
    *(uint4*)(g_xh + i) = *(uint4*)h;
}

// ---------------- kernel: fp32 -> fp16 weight convert (all 6 tensors, one launch) ----------------
__global__ void cvt_w_kernel(const float* __restrict__ Wg_s, const float* __restrict__ Wu_s,
                             const float* __restrict__ Wd_s, const float* __restrict__ Wg,
                             const float* __restrict__ Wu,   const float* __restrict__ Wd) {
    int b = blockIdx.x;
    const float* src;
    __half* dst;
    if (b < 1024)       { src = Wg_s; dst = g_Wgh + (size_t)NE * IDIM * HDIM; }
    else if (b < 2048)  { src = Wu_s; dst = g_Wuh + (size_t)NE * IDIM * HDIM; b -= 1024; }
    else if (b < 3072)  { src = Wd_s; dst = g_Wdh + (size_t)NE * HDIM * IDIM; b -= 2048; }
    else if (b < 11264) { src = Wg;   dst = g_Wgh; b -= 3072; }
    else if (b < 19456) { src = Wu;   dst = g_Wuh; b -= 11264; }
    else                { src = Wd;   dst = g_Wdh; b -= 19456; }
    size_t i = ((size_t)b * 256 + threadIdx.x) * 8;
    float4 v0 = *(const float4*)(src + i);
    float4 v1 = *(const float4*)(src + i + 4);
    __half2 h[4];
    h[0] = __floats2half2_rn(v0.x, v0.y);
    h[1] = __floats2half2_rn(v0.z, v0.w);
    h[2] = __floats2half2_rn(v1.x, v1.y);
    h[3] = __floats2half2_rn(v1.z, v1.w);
    *(uint4*)(dst + i) = *(uint4*)h;
}

// ---------------- kernel: router (sigmoid top-2) ----------------
__global__ void router_kernel(const float* __restrict__ x,
                              const float* __restrict__ Wr,
                              const float* __restrict__ rb) {
    __shared__ float sWr[NE][HDIM];
    int tid = threadIdx.x;
    for (int i = tid * 4; i < NE * HDIM; i += blockDim.x * 4)
        *(float4*)&sWr[0][i] = *(const float4*)&Wr[i];
    __syncthreads();

    int wid = tid >> 5, lane = tid & 31;
    int t = blockIdx.x * 8 + wid;
    const float* xr = x + (size_t)t * HDIM;

    float acc[NE];
#pragma unroll
    for (int e = 0; e < NE; e++) acc[e] = 0.f;
    for (int k = lane; k < HDIM; k += 32) {
        float xv = xr[k];
#pragma unroll
        for (int e = 0; e < NE; e++) acc[e] += xv * sWr[e][k];
    }
#pragma unroll
    for (int e = 0; e < NE; e++) {
#pragma unroll
        for (int off = 16; off > 0; off >>= 1)
            acc[e] += __shfl_xor_sync(0xffffffffu, acc[e], off);
    }
    if (lane == 0) {
        float best1 = -1e30f, best2 = -1e30f;
        int e1 = -1, e2 = -1;
#pragma unroll
        for (int e = 0; e < NE; e++) {
            float l = acc[e] + rb[e];
            if (l > best1) { best2 = best1; e2 = e1; best1 = l; e1 = e; }
            else if (l > best2) { best2 = l; e2 = e; }
        }
        float w1 = 1.f / (1.f + __expf(-best1));
        float w2 = 1.f / (1.f + __expf(-best2));
        int p1 = atomicAdd(&g_cnt[e1], 1);
        g_tok[e1 * TOKS + p1] = t;  g_wt[e1 * TOKS + p1] = w1;
        int p2 = atomicAdd(&g_cnt[e2], 1);
        g_tok[e2 * TOKS + p2] = t;  g_wt[e2 * TOKS + p2] = w2;
    }
}

// ---------------- kernel: prefix offsets ----------------
__global__ void offs_kernel() {
    if (threadIdx.x == 0) {
        int a = 0;
        for (int e = 0; e < NE; e++) { g_off[e] = a; a += g_cnt[e]; }
        g_off[NE] = 2 * TOKS;
    }
}

// smem per stage (BK=64): A at (c*256+m)*16 c<8, B at 32768 + (c*128+n)*16
// ========== gate+up GEMM: BM=256 tokens, 64 out-cols, BK=64, 512 threads ==========
__global__ __launch_bounds__(512, 1) void gateup_kernel() {
    extern __shared__ char smem[];
    __shared__ int sTok[256];
    const uint32_t sb = smem_u32(smem);
    const int e = blockIdx.z;
    const int rows = (e == NE) ? TOKS : g_cnt[e];
    const int m0 = blockIdx.y * 256;
    if (m0 >= rows) return;
    const int n0 = blockIdx.x * 64;
    const __half* Bg = g_Wgh + (size_t)e * IDIM * HDIM;
    const __half* Bu = g_Wuh + (size_t)e * IDIM * HDIM;
    const int rowbase = g_off[e];
    const int tid = threadIdx.x, wid = tid >> 5, lane = tid & 31;
    const int wm = (wid & 7) * 32, wn = (wid >> 3) * 64;

    for (int m = tid; m < 256; m += 512) {
        int r = m0 + m;
        sTok[m] = (r < rows) ? ((e == NE) ? r : g_tok[e * TOKS + r]) : -1;
    }
    __syncthreads();

    // fill state: A 4 lines/thread (same row m, chunks ac0+2i), B 2 lines (row n, chunks bc0+4i)
    const int am = tid & 255, ac0 = tid >> 8;              // ac0 in {0,1}
    const int bn = tid & 127, bc0 = tid >> 7;              // bc0 in {0..3}
    const int atok = sTok[am];
    const __half* asrc = g_xh + (atok >= 0 ? (size_t)atok * HDIM : 0) + ac0 * 8;
    const int asz = (atok >= 0) ? 16 : 0;
    const int bmat = (bn >> 5) & 1;
    const int bcol = n0 + ((bn >> 6) << 5) + (bn & 31);
    const __half* bsrc = (bmat ? Bu : Bg) + (size_t)bcol * HDIM + bc0 * 8;

    float acc[2][8][4];
#pragma unroll
    for (int mt = 0; mt < 2; mt++)
#pragma unroll
        for (int nt = 0; nt < 8; nt++)
#pragma unroll
            for (int i = 0; i < 4; i++) acc[mt][nt][i] = 0.f;

    const int KT = HDIM / 64;
    int fetch = 0;
#pragma unroll
    for (; fetch < STG - 1; fetch++) {
        uint32_t st = sb + fetch * STAGE_BYTES;
#pragma unroll
        for (int i = 0; i < 4; i++)
            cp16(st + (uint32_t)((ac0 + 2 * i) * 256 + am) * 16, asrc + fetch * 64 + i * 16, asz);
#pragma unroll
        for (int i = 0; i < 2; i++)
            cp16(st + 32768u + (uint32_t)((bc0 + 4 * i) * 128 + bn) * 16, bsrc + fetch * 64 + i * 32, 16);
        cp_commit();
    }

    for (int c = 0; c < KT; c++) {
        cp_wait();
        __syncthreads();
        if (fetch < KT) {
            uint32_t st = sb + (fetch % STG) * STAGE_BYTES;
#pragma unroll
            for (int i = 0; i < 4; i++)
                cp16(st + (uint32_t)((ac0 + 2 * i) * 256 + am) * 16, asrc + fetch * 64 + i * 16, asz);
#pragma unroll
            for (int i = 0; i < 2; i++)
                cp16(st + 32768u + (uint32_t)((bc0 + 4 * i) * 128 + bn) * 16, bsrc + fetch * 64 + i * 32, 16);
            fetch++;
        }
        cp_commit();

        const uint32_t Ab = sb + (c % STG) * STAGE_BYTES;
        const uint32_t Bb = Ab + 32768;
#pragma unroll
        for (int s = 0; s < 4; s++) {
            const int cb = 2 * s;
            uint32_t a[2][4];
#pragma unroll
            for (int mt = 0; mt < 2; mt++) {
                int mrow = wm + mt * 16 + (lane & 7) + ((lane >> 3) & 1) * 8;
                int mc = cb + ((lane >> 4) & 1);
                ldsm4(a[mt], Ab + (uint32_t)(mc * 256 + mrow) * 16);
            }
            uint32_t b[8][2];
#pragma unroll
            for (int p = 0; p < 4; p++) {
                int nrow = wn + p * 16 + (lane & 7) + ((lane >> 4) & 1) * 8;
                int nc = cb + ((lane >> 3) & 1);
                uint32_t t[4];
                ldsm4(t, Bb + (uint32_t)(nc * 128 + nrow) * 16);
                b[2 * p][0] = t[0]; b[2 * p][1] = t[1];
                b[2 * p + 1][0] = t[2]; b[2 * p + 1][1] = t[3];
            }
#pragma unroll
            for (int nt = 0; nt < 8; nt++)
#pragma unroll
                for (int mt = 0; mt < 2; mt++)
                    mma_f16(acc[mt][nt], a[mt], b[nt][0], b[nt][1]);
        }
    }

    // epilogue: h = silu(g)*u -> half
    const int cb = n0 + (wn >> 1);
#pragma unroll
    for (int mt = 0; mt < 2; mt++) {
#pragma unroll
        for (int h = 0; h < 2; h++) {
            int r = m0 + wm + mt * 16 + (lane >> 2) + h * 8;
            if (r < rows) {
                __half* hrow = g_hh + (size_t)(rowbase + r) * IDIM;
#pragma unroll
                for (int nt = 0; nt < 4; nt++) {
                    int col = cb + nt * 8 + 2 * (lane & 3);
                    float g0 = acc[mt][nt][h * 2 + 0], g1 = acc[mt][nt][h * 2 + 1];
                    float u0 = acc[mt][nt + 4][h * 2 + 0], u1 = acc[mt][nt + 4][h * 2 + 1];
                    float h0 = g0 * u0 / (1.f + __expf(-g0));
                    float h1 = g1 * u1 / (1.f + __expf(-g1));
                    *(__half2*)(hrow + col) = __floats2half2_rn(h0, h1);
                }
            }
        }
    }
}

// ========== down GEMM: BM=256, BN=128 over HDIM, BK=64 over IDIM, 512 threads ==========
__global__ __launch_bounds__(512, 1) void down_kernel(float* __restrict__ out, int shared_mode) {
    extern __shared__ char smem[];
    __shared__ int   sTok[256];
    __shared__ float sW[256];
    const uint32_t sb = smem_u32(smem);
    const int e = shared_mode ? NE : blockIdx.z;
    const int rows = shared_mode ? TOKS : g_cnt[e];
    const int m0 = blockIdx.y * 256;
    if (m0 >= rows) return;
    const int n0 = blockIdx.x * 128;
    const __half* Bw = g_Wdh + (size_t)e * HDIM * IDIM;
    const int rowbase = shared_mode ? 2 * TOKS : g_off[e];
    const int tid = threadIdx.x, wid = tid >> 5, lane = tid & 31;
    const int wm = (wid & 7) * 32, wn = (wid >> 3) * 64;

    for (int m = tid; m < 256; m += 512) {
        int r = m0 + m;
        if (r < rows) {
            sTok[m] = shared_mode ? r : g_tok[e * TOKS + r];
            sW[m]   = shared_mode ? 1.f : g_wt[e * TOKS + r];
        } else { sTok[m] = -1; sW[m] = 0.f; }
    }
    __syncthreads();

    const int am = tid & 255, ac0 = tid >> 8;
    const int bn = tid & 127, bc0 = tid >> 7;
    const __half* asrc = g_hh + (size_t)(rowbase + m0 + am) * IDIM + ac0 * 8;
    const __half* bsrc = Bw + (size_t)(n0 + bn) * IDIM + bc0 * 8;

    float acc[2][8][4];
#pragma unroll
    for (int mt = 0; mt < 2; mt++)
#pragma unroll
        for (int nt = 0; nt < 8; nt++)
#pragma unroll
            for (int i = 0; i < 4; i++) acc[mt][nt][i] = 0.f;

    const int KT = IDIM / 64;
    int fetch = 0;
#pragma unroll
    for (; fetch < STG - 1; fetch++) {
        uint32_t st = sb + fetch * STAGE_BYTES;
#pragma unroll
        for (int i = 0; i < 4; i++)
            cp16(st + (uint32_t)((ac0 + 2 * i) * 256 + am) * 16, asrc + fetch * 64 + i * 16, 16);
#pragma unroll
        for (int i = 0; i < 2; i++)
            cp16(st + 32768u + (uint32_t)((bc0 + 4 * i) * 128 + bn) * 16, bsrc + fetch * 64 + i * 32, 16);
        cp_commit();
    }

    for (int c = 0; c < KT; c++) {
        cp_wait();
        __syncthreads();
        if (fetch < KT) {
            uint32_t st = sb + (fetch % STG) * STAGE_BYTES;
#pragma unroll
            for (int i = 0; i < 4; i++)
                cp16(st + (uint32_t)((ac0 + 2 * i) * 256 + am) * 16, asrc + fetch * 64 + i * 16, 16);
#pragma unroll
            for (int i = 0; i < 2; i++)
                cp16(st + 32768u + (uint32_t)((bc0 + 4 * i) * 128 + bn) * 16, bsrc + fetch * 64 + i * 32, 16);
            fetch++;
        }
        cp_commit();

        const uint32_t Ab = sb + (c % STG) * STAGE_BYTES;
        const uint32_t Bb = Ab + 32768;
#pragma unroll
        for (int s = 0; s < 4; s++) {
            const int cb = 2 * s;
            uint32_t a[2][4];
#pragma unroll
            for (int mt = 0; mt < 2; mt++) {
                int mrow = wm + mt * 16 + (lane & 7) + ((lane >> 3) & 1) * 8;
                int mc = cb + ((lane >> 4) & 1);
                ldsm4(a[mt], Ab + (uint32_t)(mc * 256 + mrow) * 16);
            }
            uint32_t b[8][2];
#pragma unroll
            for (int p = 0; p < 4; p++) {
                int nrow = wn + p * 16 + (lane & 7) + ((lane >> 4) & 1) * 8;
                int nc = cb + ((lane >> 3) & 1);
                uint32_t t[4];
                ldsm4(t, Bb + (uint32_t)(nc * 128 + nrow) * 16);
                b[2 * p][0] = t[0]; b[2 * p][1] = t[1];
                b[2 * p + 1][0] = t[2]; b[2 * p + 1][1] = t[3];
            }
#pragma unroll
            for (int nt = 0; nt < 8; nt++)
#pragma unroll
                for (int mt = 0; mt < 2; mt++)
                    mma_f16(acc[mt][nt], a[mt], b[nt][0], b[nt][1]);
        }
    }

    // epilogue: direct to out
#pragma unroll
    for (int mt = 0; mt < 2; mt++) {
#pragma unroll
        for (int h = 0; h < 2; h++) {
            int ml = wm + mt * 16 + (lane >> 2) + h * 8;
            int r = m0 + ml;
            if (r < rows) {
                int tok = sTok[ml];
                float w = sW[ml];
                float* drow = out + (size_t)tok * HDIM;
#pragma unroll
                for (int nt = 0; nt < 8; nt++) {
                    int col = n0 + wn + nt * 8 + 2 * (lane & 3);
                    float v0 = acc[mt][nt][h * 2 + 0];
                    float v1 = acc[mt][nt][h * 2 + 1];
                    if (shared_mode) {
                        *(float2*)(drow + col) = make_float2(v0, v1);
                    } else {
                        atomicAdd(drow + col + 0, w * v0);
                        atomicAdd(drow + col + 1, w * v1);
                    }
                }
            }
        }
    }
}

// ---------------- launch ----------------
extern "C" void kernel_launch(void* const* d_in, const int* in_sizes, int n_in,
                              void* d_out, int out_size) {
    (void)in_sizes; (void)n_in; (void)out_size;
    const float* x    = (const float*)d_in[0];
    const float* Wg_s = (const float*)d_in[1];
    const float* Wu_s = (const float*)d_in[2];
    const float* Wd_s = (const float*)d_in[3];
    const float* Wg   = (const float*)d_in[4];
    const float* Wu   = (const float*)d_in[5];
    const float* Wd   = (const float*)d_in[6];
    const float* Wr   = (const float*)d_in[7];
    const float* rb   = (const float*)d_in[8];
    float* out = (float*)d_out;

    cudaFuncSetAttribute(gateup_kernel, cudaFuncAttributeMaxDynamicSharedMemorySize, SMEM_BYTES);
    cudaFuncSetAttribute(down_kernel,   cudaFuncAttributeMaxDynamicSharedMemorySize, SMEM_BYTES);

    zero_cnt_kernel<<<1, 32>>>();
    cvt_x_kernel<<<TOKS * HDIM / 2048, 256>>>(x);
    cvt_w_kernel<<<27648, 256>>>(Wg_s, Wu_s, Wd_s, Wg, Wu, Wd);
    router_kernel<<<TOKS / 8, 256>>>(x, Wr, rb);
    offs_kernel<<<1, 32>>>();
    gateup_kernel<<<dim3(IDIM / 64, TOKS / 256, NE + 1), 512, SMEM_BYTES>>>();
    down_kernel<<<dim3(HDIM / 128, TOKS / 256, 1), 512, SMEM_BYTES>>>(out, 1);
    down_kernel<<<dim3(HDIM / 128, TOKS / 256, NE), 512, SMEM_BYTES>>>(out, 0);
}

// round 8
// speedup vs baseline: 1.0104x; 1.0104x over previous
#include <cuda_runtime.h>
#include <cuda_fp16.h>
#include <cstdint>

#define TOKS 16384
#define HDIM 1024
#define IDIM 2048
#define NE   8
#define STG  6
#define STAGE_BYTES 24576           // A: 4 chunks x 256 rows x 16B = 16KB, B: 4 x 128 x 16B = 8KB
#define SMEM_BYTES  (STG * STAGE_BYTES)

// ---------------- static scratch ----------------
__device__ int   g_cnt[16];
__device__ int   g_off[16];
__device__ int   g_tok[NE * TOKS];
__device__ float g_wt [NE * TOKS];
__device__ __align__(256) __half g_xh[(size_t)TOKS * HDIM];
__device__ __align__(256) __half g_Wgh[(size_t)(NE + 1) * IDIM * HDIM];  // slot NE = shared
__device__ __align__(256) __half g_Wuh[(size_t)(NE + 1) * IDIM * HDIM];
__device__ __align__(256) __half g_Wdh[(size_t)(NE + 1) * HDIM * IDIM];
__device__ __align__(256) __half g_hh[(size_t)3 * TOKS * IDIM];  // routed packed, shared at 2*TOKS

// ---------------- helpers ----------------
__device__ __forceinline__ uint32_t smem_u32(const void* p) {
    uint32_t a;
    asm("{ .reg .u64 t; cvta.to.shared.u64 t, %1; cvt.u32.u64 %0, t; }" : "=r"(a) : "l"(p));
    return a;
}
__device__ __forceinline__ void cp16(uint32_t dst, const __half* src, int sz) {
    asm volatile("cp.async.cg.shared.global [%0], [%1], 16, %2;"
                 :: "r"(dst), "l"(src), "r"(sz) : "memory");
}
__device__ __forceinline__ void cp_commit() { asm volatile("cp.async.commit_group;" ::: "memory"); }
__device__ __forceinline__ void cp_wait()   { asm volatile("cp.async.wait_group %0;" :: "n"(STG - 2) : "memory"); }

__device__ __forceinline__ void ldsm4(uint32_t* r, uint32_t addr) {
    asm volatile("ldmatrix.sync.aligned.m8n8.x4.shared.b16 {%0,%1,%2,%3}, [%4];"
                 : "=r"(r[0]), "=r"(r[1]), "=r"(r[2]), "=r"(r[3]) : "r"(addr));
}
__device__ __forceinline__ void mma_f16(float* c, const uint32_t* a, uint32_t b0, uint32_t b1) {
    asm volatile(
        "mma.sync.aligned.m16n8k16.row.col.f32.f16.f16.f32 "
        "{%0,%1,%2,%3}, {%4,%5,%6,%7}, {%8,%9}, {%0,%1,%2,%3};\n"
        : "+f"(c[0]), "+f"(c[1]), "+f"(c[2]), "+f"(c[3])
        : "r"(a[0]), "r"(a[1]), "r"(a[2]), "r"(a[3]), "r"(b0), "r"(b1));
}

// ---------------- kernel: zero counters ----------------
__global__ void zero_cnt_kernel() {
    if (threadIdx.x < 16) g_cnt[threadIdx.x] = 0;
}

// ---------------- kernel: fp32 -> fp16 x convert ----------------
__global__ void cvt_x_kernel(const float* __restrict__ src) {
    size_t i = ((size_t)blockIdx.x * 256 + threadIdx.x) * 8;
    float4 v0 = *(const float4*)(src + i);
    float4 v1 = *(const float4*)(src + i + 4);
    __half2 h[4];
    h[0] = __floats2half2_rn(v0.x, v0.y);
    h[1] = __floats2half2_rn(v0.z, v0.w);
    h[2] = __floats2half2_rn(v1.x, v1.y);
    h[3] = __floats2half2_rn(v1.z, v1.w);
    *(uint4*)(g_xh + i) = *(uint4*)h;
}

// ---------------- kernel: fp32 -> fp16 weight convert (all 6 tensors, one launch) ----------------
// 512 threads, 4096 fp32 per block.
// ranges: Wgs[0,512) Wus[512,1024) Wds[1024,1536) Wg[1536,5632) Wu[5632,9728) Wd[9728,13824)
__global__ void cvt_w_kernel(const float* __restrict__ Wg_s, const float* __restrict__ Wu_s,
                             const float* __restrict__ Wd_s, const float* __restrict__ Wg,
                             const float* __restrict__ Wu,   const float* __restrict__ Wd) {
    int b = blockIdx.x;
    const float* src;
    __half* dst;
    if (b < 512)        { src = Wg_s; dst = g_Wgh + (size_t)NE * IDIM * HDIM; }
    else if (b < 1024)  { src = Wu_s; dst = g_Wuh + (size_t)NE * IDIM * HDIM; b -= 512; }
    else if (b < 1536)  { src = Wd_s; dst = g_Wdh + (size_t)NE * HDIM * IDIM; b -= 1024; }
    else if (b < 5632)  { src = Wg;   dst = g_Wgh; b -= 1536; }
    else if (b < 9728)  { src = Wu;   dst = g_Wuh; b -= 5632; }
    else                { src = Wd;   dst = g_Wdh; b -= 9728; }
    size_t i = ((size_t)b * 512 + threadIdx.x) * 8;
    float4 v0 = *(const float4*)(src + i);
    float4 v1 = *(const float4*)(src + i + 4);
    __half2 h[4];
    h[0] = __floats2half2_rn(v0.x, v0.y);
    h[1] = __floats2half2_rn(v0.z, v0.w);
    h[2] = __floats2half2_rn(v1.x, v1.y);
    h[3] = __floats2half2_rn(v1.z, v1.w);
    *(uint4*)(dst + i) = *(uint4*)h;
}

// ---------------- kernel: router (sigmoid top-2) ----------------
__global__ void router_kernel(const float* __restrict__ x,
                              const float* __restrict__ Wr,
                              const float* __restrict__ rb) {
    __shared__ float sWr[NE][HDIM];
    int tid = threadIdx.x;
    for (int i = tid * 4; i < NE * HDIM; i += blockDim.x * 4)
        *(float4*)&sWr[0][i] = *(const float4*)&Wr[i];
    __syncthreads();

    int wid = tid >> 5, lane = tid & 31;
    int t = blockIdx.x * 8 + wid;
    const float* xr = x + (size_t)t * HDIM;

    float acc[NE];
#pragma unroll
    for (int e = 0; e < NE; e++) acc[e] = 0.f;
    for (int k = lane; k < HDIM; k += 32) {
        float xv = xr[k];
#pragma unroll
        for (int e = 0; e < NE; e++) acc[e] += xv * sWr[e][k];
    }
#pragma unroll
    for (int e = 0; e < NE; e++) {
#pragma unroll
        for (int off = 16; off > 0; off >>= 1)
            acc[e] += __shfl_xor_sync(0xffffffffu, acc[e], off);
    }
    if (lane == 0) {
        float best1 = -1e30f, best2 = -1e30f;
        int e1 = -1, e2 = -1;
#pragma unroll
        for (int e = 0; e < NE; e++) {
            float l = acc[e] + rb[e];
            if (l > best1) { best2 = best1; e2 = e1; best1 = l; e1 = e; }
            else if (l > best2) { best2 = l; e2 = e; }
        }
        float w1 = 1.f / (1.f + __expf(-best1));
        float w2 = 1.f / (1.f + __expf(-best2));
        int p1 = atomicAdd(&g_cnt[e1], 1);
        g_tok[e1 * TOKS + p1] = t;  g_wt[e1 * TOKS + p1] = w1;
        int p2 = atomicAdd(&g_cnt[e2], 1);
        g_tok[e2 * TOKS + p2] = t;  g_wt[e2 * TOKS + p2] = w2;
    }
}

// ---------------- kernel: prefix offsets ----------------
__global__ void offs_kernel() {
    if (threadIdx.x == 0) {
        int a = 0;
        for (int e = 0; e < NE; e++) { g_off[e] = a; a += g_cnt[e]; }
        g_off[NE] = 2 * TOKS;
    }
}

// smem per stage: A at (c*256+m)*16, B at 16384 + (c*128+n)*16
// ========== gate+up GEMM: BM=256 tokens, 64 out-cols (gate+up interleaved), 512 threads ==========
__global__ __launch_bounds__(512, 1) void gateup_kernel() {
    extern __shared__ char smem[];
    __shared__ int sTok[256];
    const uint32_t sb = smem_u32(smem);
    const int e = blockIdx.z;
    const int rows = (e == NE) ? TOKS : g_cnt[e];
    const int m0 = blockIdx.y * 256;
    if (m0 >= rows) return;
    const int n0 = blockIdx.x * 64;
    const __half* Bg = g_Wgh + (size_t)e * IDIM * HDIM;
    const __half* Bu = g_Wuh + (size_t)e * IDIM * HDIM;
    const int rowbase = g_off[e];
    const int tid = threadIdx.x, wid = tid >> 5, lane = tid & 31;
    const int wm = (wid & 7) * 32, wn = (wid >> 3) * 64;

    for (int m = tid; m < 256; m += 512) {
        int r = m0 + m;
        sTok[m] = (r < rows) ? ((e == NE) ? r : g_tok[e * TOKS + r]) : -1;
    }
    __syncthreads();

    // fill: A 1024 lines (2/thread), B 512 lines (1/thread)
    const __half* asrc[2]; int asz[2]; uint32_t aoff[2];
    const __half* bsrc; uint32_t boff;
#pragma unroll
    for (int i = 0; i < 2; i++) {
        int idx = tid + i * 512;
        int m = idx & 255, c = idx >> 8;
        int tok = sTok[m];
        asrc[i] = g_xh + (tok >= 0 ? (size_t)tok * HDIM : 0) + c * 8;
        asz[i]  = (tok >= 0) ? 16 : 0;
        aoff[i] = (uint32_t)(c * 256 + m) * 16;
    }
    {
        int n = tid & 127, c = tid >> 7;
        int mat = (n >> 5) & 1;
        int col = n0 + ((n >> 6) << 5) + (n & 31);
        bsrc = (mat ? Bu : Bg) + (size_t)col * HDIM + c * 8;
        boff = 16384u + (uint32_t)(c * 128 + n) * 16;
    }

    float acc[2][8][4];
#pragma unroll
    for (int mt = 0; mt < 2; mt++)
#pragma unroll
        for (int nt = 0; nt < 8; nt++)
#pragma unroll
            for (int i = 0; i < 4; i++) acc[mt][nt][i] = 0.f;

    const int KT = HDIM / 32;
    int fetch = 0;
#pragma unroll
    for (; fetch < STG - 1; fetch++) {
        uint32_t st = sb + fetch * STAGE_BYTES;
#pragma unroll
        for (int i = 0; i < 2; i++) cp16(st + aoff[i], asrc[i] + fetch * 32, asz[i]);
        cp16(st + boff, bsrc + fetch * 32, 16);
        cp_commit();
    }

    for (int c = 0; c < KT; c++) {
        cp_wait();
        __syncthreads();
        if (fetch < KT) {
            uint32_t st = sb + (fetch % STG) * STAGE_BYTES;
#pragma unroll
            for (int i = 0; i < 2; i++) cp16(st + aoff[i], asrc[i] + fetch * 32, asz[i]);
            cp16(st + boff, bsrc + fetch * 32, 16);
            fetch++;
        }
        cp_commit();

        const uint32_t Ab = sb + (c % STG) * STAGE_BYTES;
        const uint32_t Bb = Ab + 16384;
#pragma unroll
        for (int s = 0; s < 2; s++) {
            const int cb = 2 * s;
            uint32_t a[2][4];
#pragma unroll
            for (int mt = 0; mt < 2; mt++) {
                int mrow = wm + mt * 16 + (lane & 7) + ((lane >> 3) & 1) * 8;
                int mc = cb + ((lane >> 4) & 1);
                ldsm4(a[mt], Ab + (uint32_t)(mc * 256 + mrow) * 16);
            }
            uint32_t b[8][2];
#pragma unroll
            for (int p = 0; p < 4; p++) {
                int nrow = wn + p * 16 + (lane & 7) + ((lane >> 4) & 1) * 8;
                int nc = cb + ((lane >> 3) & 1);
                uint32_t t[4];
                ldsm4(t, Bb + (uint32_t)(nc * 128 + nrow) * 16);
                b[2 * p][0] = t[0]; b[2 * p][1] = t[1];
                b[2 * p + 1][0] = t[2]; b[2 * p + 1][1] = t[3];
            }
#pragma unroll
            for (int nt = 0; nt < 8; nt++)
#pragma unroll
                for (int mt = 0; mt < 2; mt++)
                    mma_f16(acc[mt][nt], a[mt], b[nt][0], b[nt][1]);
        }
    }

    // epilogue: h = silu(g)*u -> half
    const int cb = n0 + (wn >> 1);
#pragma unroll
    for (int mt = 0; mt < 2; mt++) {
#pragma unroll
        for (int h = 0; h < 2; h++) {
            int r = m0 + wm + mt * 16 + (lane >> 2) + h * 8;
            if (r < rows) {
                __half* hrow = g_hh + (size_t)(rowbase + r) * IDIM;
#pragma unroll
                for (int nt = 0; nt < 4; nt++) {
                    int col = cb + nt * 8 + 2 * (lane & 3);
                    float g0 = acc[mt][nt][h * 2 + 0], g1 = acc[mt][nt][h * 2 + 1];
                    float u0 = acc[mt][nt + 4][h * 2 + 0], u1 = acc[mt][nt + 4][h * 2 + 1];
                    float h0 = g0 * u0 / (1.f + __expf(-g0));
                    float h1 = g1 * u1 / (1.f + __expf(-g1));
                    *(__half2*)(hrow + col) = __floats2half2_rn(h0, h1);
                }
            }
        }
    }
}

// ========== down GEMM: BM=256, BN=128 over HDIM, K over IDIM, 512 threads ==========
__global__ __launch_bounds__(512, 1) void down_kernel(float* __restrict__ out, int shared_mode) {
    extern __shared__ char smem[];
    __shared__ int   sTok[256];
    __shared__ float sW[256];
    const uint32_t sb = smem_u32(smem);
    const int e = shared_mode ? NE : blockIdx.z;
    const int rows = shared_mode ? TOKS : g_cnt[e];
    const int m0 = blockIdx.y * 256;
    if (m0 >= rows) return;
    const int n0 = blockIdx.x * 128;
    const __half* Bw = g_Wdh + (size_t)e * HDIM * IDIM;
    const int rowbase = shared_mode ? 2 * TOKS : g_off[e];
    const int tid = threadIdx.x, wid = tid >> 5, lane = tid & 31;
    const int wm = (wid & 7) * 32, wn = (wid >> 3) * 64;

    for (int m = tid; m < 256; m += 512) {
        int r = m0 + m;
        if (r < rows) {
            sTok[m] = shared_mode ? r : g_tok[e * TOKS + r];
            sW[m]   = shared_mode ? 1.f : g_wt[e * TOKS + r];
        } else { sTok[m] = -1; sW[m] = 0.f; }
    }
    __syncthreads();

    const __half* asrc[2]; uint32_t aoff[2];
    const __half* bsrc; uint32_t boff;
#pragma unroll
    for (int i = 0; i < 2; i++) {
        int idx = tid + i * 512;
        int m = idx & 255, c = idx >> 8;
        asrc[i] = g_hh + (size_t)(rowbase + m0 + m) * IDIM + c * 8;
        aoff[i] = (uint32_t)(c * 256 + m) * 16;
    }
    {
        int n = tid & 127, c = tid >> 7;
        bsrc = Bw + (size_t)(n0 + n) * IDIM + c * 8;
        boff = 16384u + (uint32_t)(c * 128 + n) * 16;
    }

    float acc[2][8][4];
#pragma unroll
    for (int mt = 0; mt < 2; mt++)
#pragma unroll
        for (int nt = 0; nt < 8; nt++)
#pragma unroll
            for (int i = 0; i < 4; i++) acc[mt][nt][i] = 0.f;

    const int KT = IDIM / 32;
    int fetch = 0;
#pragma unroll
    for (; fetch < STG - 1; fetch++) {
        uint32_t st = sb + fetch * STAGE_BYTES;
#pragma unroll
        for (int i = 0; i < 2; i++) cp16(st + aoff[i], asrc[i] + fetch * 32, 16);
        cp16(st + boff, bsrc + fetch * 32, 16);
        cp_commit();
    }

    for (int c = 0; c < KT; c++) {
        cp_wait();
        __syncthreads();
        if (fetch < KT) {
            uint32_t st = sb + (fetch % STG) * STAGE_BYTES;
#pragma unroll
            for (int i = 0; i < 2; i++) cp16(st + aoff[i], asrc[i] + fetch * 32, 16);
            cp16(st + boff, bsrc + fetch * 32, 16);
            fetch++;
        }
        cp_commit();

        const uint32_t Ab = sb + (c % STG) * STAGE_BYTES;
        const uint32_t Bb = Ab + 16384;
#pragma unroll
        for (int s = 0; s < 2; s++) {
            const int cb = 2 * s;
            uint32_t a[2][4];
#pragma unroll
            for (int mt = 0; mt < 2; mt++) {
                int mrow = wm + mt * 16 + (lane & 7) + ((lane >> 3) & 1) * 8;
                int mc = cb + ((lane >> 4) & 1);
                ldsm4(a[mt], Ab + (uint32_t)(mc * 256 + mrow) * 16);
            }
            uint32_t b[8][2];
#pragma unroll
            for (int p = 0; p < 4; p++) {
                int nrow = wn + p * 16 + (lane & 7) + ((lane >> 4) & 1) * 8;
                int nc = cb + ((lane >> 3) & 1);
                uint32_t t[4];
                ldsm4(t, Bb + (uint32_t)(nc * 128 + nrow) * 16);
                b[2 * p][0] = t[0]; b[2 * p][1] = t[1];
                b[2 * p + 1][0] = t[2]; b[2 * p + 1][1] = t[3];
            }
#pragma unroll
            for (int nt = 0; nt < 8; nt++)
#pragma unroll
                for (int mt = 0; mt < 2; mt++)
                    mma_f16(acc[mt][nt], a[mt], b[nt][0], b[nt][1]);
        }
    }

    // epilogue: direct to out
#pragma unroll
    for (int mt = 0; mt < 2; mt++) {
#pragma unroll
        for (int h = 0; h < 2; h++) {
            int ml = wm + mt * 16 + (lane >> 2) + h * 8;
            int r = m0 + ml;
            if (r < rows) {
                int tok = sTok[ml];
                float w = sW[ml];
                float* drow = out + (size_t)tok * HDIM;
#pragma unroll
                for (int nt = 0; nt < 8; nt++) {
                    int col = n0 + wn + nt * 8 + 2 * (lane & 3);
                    float v0 = acc[mt][nt][h * 2 + 0];
                    float v1 = acc[mt][nt][h * 2 + 1];
                    if (shared_mode) {
                        *(float2*)(drow + col) = make_float2(v0, v1);
                    } else {
                        atomicAdd(drow + col + 0, w * v0);
                        atomicAdd(drow + col + 1, w * v1);
                    }
                }
            }
        }
    }
}

// ---------------- launch ----------------
extern "C" void kernel_launch(void* const* d_in, const int* in_sizes, int n_in,
                              void* d_out, int out_size) {
    (void)in_sizes; (void)n_in; (void)out_size;
    const float* x    = (const float*)d_in[0];
    const float* Wg_s = (const float*)d_in[1];
    const float* Wu_s = (const float*)d_in[2];
    const float* Wd_s = (const float*)d_in[3];
    const float* Wg   = (const float*)d_in[4];
    const float* Wu   = (const float*)d_in[5];
    const float* Wd   = (const float*)d_in[6];
    const float* Wr   = (const float*)d_in[7];
    const float* rb   = (const float*)d_in[8];
    float* out = (float*)d_out;

    cudaFuncSetAttribute(gateup_kernel, cudaFuncAttributeMaxDynamicSharedMemorySize, SMEM_BYTES);
    cudaFuncSetAttribute(down_kernel,   cudaFuncAttributeMaxDynamicSharedMemorySize, SMEM_BYTES);

    zero_cnt_kernel<<<1, 32>>>();                                   // launch 1
    cvt_x_kernel<<<TOKS * HDIM / 2048, 256>>>(x);                   // launch 2
    cvt_w_kernel<<<13824, 512>>>(Wg_s, Wu_s, Wd_s, Wg, Wu, Wd);     // launch 3
    router_kernel<<<TOKS / 8, 256>>>(x, Wr, rb);                    // launch 4
    offs_kernel<<<1, 32>>>();                                       // launch 5
    gateup_kernel<<<dim3(IDIM / 64, TOKS / 256, NE + 1), 512, SMEM_BYTES>>>();   // launch 6 (profiled)
    down_kernel<<<dim3(HDIM / 128, TOKS / 256, 1), 512, SMEM_BYTES>>>(out, 1);
    down_kernel<<<dim3(HDIM / 128, TOKS / 256, NE), 512, SMEM_BYTES>>>(out, 0);
}

// round 9
// speedup vs baseline: 1.0553x; 1.0445x over previous
#include <cuda_runtime.h>
#include <cuda_fp16.h>
#include <cstdint>

#define TOKS 16384
#define HDIM 1024
#define IDIM 2048
#define NE   8
#define STG  4
#define STAGE_BYTES 24576           // A: 4 chunks x 256 rows x 16B = 16KB, B: 4 x 128 x 16B = 8KB
#define SMEM_BYTES  (STG * STAGE_BYTES)

// ---------------- static scratch ----------------
__device__ int   g_cnt[16];
__device__ int   g_off[16];
__device__ int   g_tok[NE * TOKS];
__device__ float g_wt [NE * TOKS];
__device__ __align__(256) __half g_xh[(size_t)TOKS * HDIM];
__device__ __align__(256) __half g_Wgh[(size_t)(NE + 1) * IDIM * HDIM];  // slot NE = shared
__device__ __align__(256) __half g_Wuh[(size_t)(NE + 1) * IDIM * HDIM];
__device__ __align__(256) __half g_Wdh[(size_t)(NE + 1) * HDIM * IDIM];
__device__ __align__(256) __half g_hh[(size_t)3 * TOKS * IDIM];  // routed packed, shared at 2*TOKS

// ---------------- helpers ----------------
__device__ __forceinline__ uint32_t smem_u32(const void* p) {
    uint32_t a;
    asm("{ .reg .u64 t; cvta.to.shared.u64 t, %1; cvt.u32.u64 %0, t; }" : "=r"(a) : "l"(p));
    return a;
}
__device__ __forceinline__ void cp16(uint32_t dst, const __half* src, int sz) {
    asm volatile("cp.async.cg.shared.global [%0], [%1], 16, %2;"
                 :: "r"(dst), "l"(src), "r"(sz) : "memory");
}
__device__ __forceinline__ void cp_commit() { asm volatile("cp.async.commit_group;" ::: "memory"); }
__device__ __forceinline__ void cp_wait()   { asm volatile("cp.async.wait_group %0;" :: "n"(STG - 2) : "memory"); }

__device__ __forceinline__ void ldsm4(uint32_t* r, uint32_t addr) {
    asm volatile("ldmatrix.sync.aligned.m8n8.x4.shared.b16 {%0,%1,%2,%3}, [%4];"
                 : "=r"(r[0]), "=r"(r[1]), "=r"(r[2]), "=r"(r[3]) : "r"(addr));
}
__device__ __forceinline__ void mma_f16(float* c, const uint32_t* a, uint32_t b0, uint32_t b1) {
    asm volatile(
        "mma.sync.aligned.m16n8k16.row.col.f32.f16.f16.f32 "
        "{%0,%1,%2,%3}, {%4,%5,%6,%7}, {%8,%9}, {%0,%1,%2,%3};\n"
        : "+f"(c[0]), "+f"(c[1]), "+f"(c[2]), "+f"(c[3])
        : "r"(a[0]), "r"(a[1]), "r"(a[2]), "r"(a[3]), "r"(b0), "r"(b1));
}

// ---------------- kernel: fp32 -> fp16 weight convert (all 6 tensors) + counter zeroing ----------------
// 256 threads, 2048 fp32 per block.
// ranges: Wgs[0,1024) Wus[1024,2048) Wds[2048,3072) Wg[3072,11264) Wu[11264,19456) Wd[19456,27648)
__global__ void cvt_w_kernel(const float* __restrict__ Wg_s, const float* __restrict__ Wu_s,
                             const float* __restrict__ Wd_s, const float* __restrict__ Wg,
                             const float* __restrict__ Wu,   const float* __restrict__ Wd) {
    if (blockIdx.x == 0 && threadIdx.x < 16) g_cnt[threadIdx.x] = 0;
    int b = blockIdx.x;
    const float* src;
    __half* dst;
    if (b < 1024)       { src = Wg_s; dst = g_Wgh + (size_t)NE * IDIM * HDIM; }
    else if (b < 2048)  { src = Wu_s; dst = g_Wuh + (size_t)NE * IDIM * HDIM; b -= 1024; }
    else if (b < 3072)  { src = Wd_s; dst = g_Wdh + (size_t)NE * HDIM * IDIM; b -= 2048; }
    else if (b < 11264) { src = Wg;   dst = g_Wgh; b -= 3072; }
    else if (b < 19456) { src = Wu;   dst = g_Wuh; b -= 11264; }
    else                { src = Wd;   dst = g_Wdh; b -= 19456; }
    size_t i = ((size_t)b * 256 + threadIdx.x) * 8;
    float4 v0 = *(const float4*)(src + i);
    float4 v1 = *(const float4*)(src + i + 4);
    __half2 h[4];
    h[0] = __floats2half2_rn(v0.x, v0.y);
    h[1] = __floats2half2_rn(v0.z, v0.w);
    h[2] = __floats2half2_rn(v1.x, v1.y);
    h[3] = __floats2half2_rn(v1.z, v1.w);
    *(uint4*)(dst + i) = *(uint4*)h;
}

// ---------------- kernel: router (sigmoid top-2) + fused x -> fp16 convert ----------------
__global__ void router_kernel(const float* __restrict__ x,
                              const float* __restrict__ Wr,
                              const float* __restrict__ rb) {
    __shared__ float sWr[NE][HDIM];
    int tid = threadIdx.x;
    for (int i = tid * 4; i < NE * HDIM; i += blockDim.x * 4)
        *(float4*)&sWr[0][i] = *(const float4*)&Wr[i];
    __syncthreads();

    int wid = tid >> 5, lane = tid & 31;
    int t = blockIdx.x * 8 + wid;
    const float* xr = x + (size_t)t * HDIM;
    __half* xh = g_xh + (size_t)t * HDIM;

    float acc[NE];
#pragma unroll
    for (int e = 0; e < NE; e++) acc[e] = 0.f;
#pragma unroll
    for (int i = 0; i < HDIM / 64; i++) {
        int k = 2 * lane + 64 * i;
        float2 v = *(const float2*)(xr + k);
        *(__half2*)(xh + k) = __floats2half2_rn(v.x, v.y);
#pragma unroll
        for (int e = 0; e < NE; e++) acc[e] += v.x * sWr[e][k] + v.y * sWr[e][k + 1];
    }
#pragma unroll
    for (int e = 0; e < NE; e++) {
#pragma unroll
        for (int off = 16; off > 0; off >>= 1)
            acc[e] += __shfl_xor_sync(0xffffffffu, acc[e], off);
    }
    if (lane == 0) {
        float best1 = -1e30f, best2 = -1e30f;
        int e1 = -1, e2 = -1;
#pragma unroll
        for (int e = 0; e < NE; e++) {
            float l = acc[e] + rb[e];
            if (l > best1) { best2 = best1; e2 = e1; best1 = l; e1 = e; }
            else if (l > best2) { best2 = l; e2 = e; }
        }
        float w1 = 1.f / (1.f + __expf(-best1));
        float w2 = 1.f / (1.f + __expf(-best2));
        int p1 = atomicAdd(&g_cnt[e1], 1);
        g_tok[e1 * TOKS + p1] = t;  g_wt[e1 * TOKS + p1] = w1;
        int p2 = atomicAdd(&g_cnt[e2], 1);
        g_tok[e2 * TOKS + p2] = t;  g_wt[e2 * TOKS + p2] = w2;
    }
}

// ---------------- kernel: prefix offsets ----------------
__global__ void offs_kernel() {
    if (threadIdx.x == 0) {
        int a = 0;
        for (int e = 0; e < NE; e++) { g_off[e] = a; a += g_cnt[e]; }
        g_off[NE] = 2 * TOKS;
    }
}

// smem per stage: A at (c*256+m)*16, B at 16384 + (c*128+n)*16
// ========== gate+up GEMM: BM=256 tokens, 64 out-cols (gate+up interleaved), 512 threads ==========
__global__ __launch_bounds__(512, 1) void gateup_kernel() {
    extern __shared__ char smem[];
    __shared__ int sTok[256];
    const uint32_t sb = smem_u32(smem);
    const int e = blockIdx.z;
    const int rows = (e == NE) ? TOKS : g_cnt[e];
    const int m0 = blockIdx.y * 256;
    if (m0 >= rows) return;
    const int n0 = blockIdx.x * 64;
    const __half* Bg = g_Wgh + (size_t)e * IDIM * HDIM;
    const __half* Bu = g_Wuh + (size_t)e * IDIM * HDIM;
    const int rowbase = g_off[e];
    const int tid = threadIdx.x, wid = tid >> 5, lane = tid & 31;
    const int wm = (wid & 7) * 32, wn = (wid >> 3) * 64;

    for (int m = tid; m < 256; m += 512) {
        int r = m0 + m;
        sTok[m] = (r < rows) ? ((e == NE) ? r : g_tok[e * TOKS + r]) : -1;
    }
    __syncthreads();

    // fill: A 1024 lines (2/thread), B 512 lines (1/thread)
    const __half* asrc[2]; int asz[2]; uint32_t aoff[2];
    const __half* bsrc; uint32_t boff;
#pragma unroll
    for (int i = 0; i < 2; i++) {
        int idx = tid + i * 512;
        int m = idx & 255, c = idx >> 8;
        int tok = sTok[m];
        asrc[i] = g_xh + (tok >= 0 ? (size_t)tok * HDIM : 0) + c * 8;
        asz[i]  = (tok >= 0) ? 16 : 0;
        aoff[i] = (uint32_t)(c * 256 + m) * 16;
    }
    {
        int n = tid & 127, c = tid >> 7;
        int mat = (n >> 5) & 1;
        int col = n0 + ((n >> 6) << 5) + (n & 31);
        bsrc = (mat ? Bu : Bg) + (size_t)col * HDIM + c * 8;
        boff = 16384u + (uint32_t)(c * 128 + n) * 16;
    }

    float acc[2][8][4];
#pragma unroll
    for (int mt = 0; mt < 2; mt++)
#pragma unroll
        for (int nt = 0; nt < 8; nt++)
#pragma unroll
            for (int i = 0; i < 4; i++) acc[mt][nt][i] = 0.f;

    const int KT = HDIM / 32;
    int fetch = 0;
#pragma unroll
    for (; fetch < STG - 1; fetch++) {
        uint32_t st = sb + fetch * STAGE_BYTES;
#pragma unroll
        for (int i = 0; i < 2; i++) cp16(st + aoff[i], asrc[i] + fetch * 32, asz[i]);
        cp16(st + boff, bsrc + fetch * 32, 16);
        cp_commit();
    }

    for (int c = 0; c < KT; c++) {
        cp_wait();
        __syncthreads();
        if (fetch < KT) {
            uint32_t st = sb + (fetch & (STG - 1)) * STAGE_BYTES;
#pragma unroll
            for (int i = 0; i < 2; i++) cp16(st + aoff[i], asrc[i] + fetch * 32, asz[i]);
            cp16(st + boff, bsrc + fetch * 32, 16);
            fetch++;
        }
        cp_commit();

        const uint32_t Ab = sb + (c & (STG - 1)) * STAGE_BYTES;
        const uint32_t Bb = Ab + 16384;
#pragma unroll
        for (int s = 0; s < 2; s++) {
            const int cb = 2 * s;
            uint32_t a[2][4];
#pragma unroll
            for (int mt = 0; mt < 2; mt++) {
                int mrow = wm + mt * 16 + (lane & 7) + ((lane >> 3) & 1) * 8;
                int mc = cb + ((lane >> 4) & 1);
                ldsm4(a[mt], Ab + (uint32_t)(mc * 256 + mrow) * 16);
            }
            uint32_t b[8][2];
#pragma unroll
            for (int p = 0; p < 4; p++) {
                int nrow = wn + p * 16 + (lane & 7) + ((lane >> 4) & 1) * 8;
                int nc = cb + ((lane >> 3) & 1);
                uint32_t t[4];
                ldsm4(t, Bb + (uint32_t)(nc * 128 + nrow) * 16);
                b[2 * p][0] = t[0]; b[2 * p][1] = t[1];
                b[2 * p + 1][0] = t[2]; b[2 * p + 1][1] = t[3];
            }
#pragma unroll
            for (int nt = 0; nt < 8; nt++)
#pragma unroll
                for (int mt = 0; mt < 2; mt++)
                    mma_f16(acc[mt][nt], a[mt], b[nt][0], b[nt][1]);
        }
    }

    // epilogue: h = silu(g)*u -> half
    const int cb = n0 + (wn >> 1);
#pragma unroll
    for (int mt = 0; mt < 2; mt++) {
#pragma unroll
        for (int h = 0; h < 2; h++) {
            int r = m0 + wm + mt * 16 + (lane >> 2) + h * 8;
            if (r < rows) {
                __half* hrow = g_hh + (size_t)(rowbase + r) * IDIM;
#pragma unroll
                for (int nt = 0; nt < 4; nt++) {
                    int col = cb + nt * 8 + 2 * (lane & 3);
                    float g0 = acc[mt][nt][h * 2 + 0], g1 = acc[mt][nt][h * 2 + 1];
                    float u0 = acc[mt][nt + 4][h * 2 + 0], u1 = acc[mt][nt + 4][h * 2 + 1];
                    float h0 = g0 * u0 / (1.f + __expf(-g0));
                    float h1 = g1 * u1 / (1.f + __expf(-g1));
                    *(__half2*)(hrow + col) = __floats2half2_rn(h0, h1);
                }
            }
        }
    }
}

// ========== down GEMM: BM=256, BN=128 over HDIM, K over IDIM, 512 threads ==========
__global__ __launch_bounds__(512, 1) void down_kernel(float* __restrict__ out, int shared_mode) {
    extern __shared__ char smem[];
    __shared__ int   sTok[256];
    __shared__ float sW[256];
    const uint32_t sb = smem_u32(smem);
    const int e = shared_mode ? NE : blockIdx.z;
    const int rows = shared_mode ? TOKS : g_cnt[e];
    const int m0 = blockIdx.y * 256;
    if (m0 >= rows) return;
    const int n0 = blockIdx.x * 128;
    const __half* Bw = g_Wdh + (size_t)e * HDIM * IDIM;
    const int rowbase = shared_mode ? 2 * TOKS : g_off[e];
    const int tid = threadIdx.x, wid = tid >> 5, lane = tid & 31;
    const int wm = (wid & 7) * 32, wn = (wid >> 3) * 64;

    for (int m = tid; m < 256; m += 512) {
        int r = m0 + m;
        if (r < rows) {
            sTok[m] = shared_mode ? r : g_tok[e * TOKS + r];
            sW[m]   = shared_mode ? 1.f : g_wt[e * TOKS + r];
        } else { sTok[m] = -1; sW[m] = 0.f; }
    }
    __syncthreads();

    const __half* asrc[2]; uint32_t aoff[2];
    const __half* bsrc; uint32_t boff;
#pragma unroll
    for (int i = 0; i < 2; i++) {
        int idx = tid + i * 512;
        int m = idx & 255, c = idx >> 8;
        asrc[i] = g_hh + (size_t)(rowbase + m0 + m) * IDIM + c * 8;
        aoff[i] = (uint32_t)(c * 256 + m) * 16;
    }
    {
        int n = tid & 127, c = tid >> 7;
        bsrc = Bw + (size_t)(n0 + n) * IDIM + c * 8;
        boff = 16384u + (uint32_t)(c * 128 + n) * 16;
    }

    float acc[2][8][4];
#pragma unroll
    for (int mt = 0; mt < 2; mt++)
#pragma unroll
        for (int nt = 0; nt < 8; nt++)
#pragma unroll
            for (int i = 0; i < 4; i++) acc[mt][nt][i] = 0.f;

    const int KT = IDIM / 32;
    int fetch = 0;
#pragma unroll
    for (; fetch < STG - 1; fetch++) {
        uint32_t st = sb + fetch * STAGE_BYTES;
#pragma unroll
        for (int i = 0; i < 2; i++) cp16(st + aoff[i], asrc[i] + fetch * 32, 16);
        cp16(st + boff, bsrc + fetch * 32, 16);
        cp_commit();
    }

    for (int c = 0; c < KT; c++) {
        cp_wait();
        __syncthreads();
        if (fetch < KT) {
            uint32_t st = sb + (fetch & (STG - 1)) * STAGE_BYTES;
#pragma unroll
            for (int i = 0; i < 2; i++) cp16(st + aoff[i], asrc[i] + fetch * 32, 16);
            cp16(st + boff, bsrc + fetch * 32, 16);
            fetch++;
        }
        cp_commit();

        const uint32_t Ab = sb + (c & (STG - 1)) * STAGE_BYTES;
        const uint32_t Bb = Ab + 16384;
#pragma unroll
        for (int s = 0; s < 2; s++) {
            const int cb = 2 * s;
            uint32_t a[2][4];
#pragma unroll
            for (int mt = 0; mt < 2; mt++) {
                int mrow = wm + mt * 16 + (lane & 7) + ((lane >> 3) & 1) * 8;
                int mc = cb + ((lane >> 4) & 1);
                ldsm4(a[mt], Ab + (uint32_t)(mc * 256 + mrow) * 16);
            }
            uint32_t b[8][2];
#pragma unroll
            for (int p = 0; p < 4; p++) {
                int nrow = wn + p * 16 + (lane & 7) + ((lane >> 4) & 1) * 8;
                int nc = cb + ((lane >> 3) & 1);
                uint32_t t[4];
                ldsm4(t, Bb + (uint32_t)(nc * 128 + nrow) * 16);
                b[2 * p][0] = t[0]; b[2 * p][1] = t[1];
                b[2 * p + 1][0] = t[2]; b[2 * p + 1][1] = t[3];
            }
#pragma unroll
            for (int nt = 0; nt < 8; nt++)
#pragma unroll
                for (int mt = 0; mt < 2; mt++)
                    mma_f16(acc[mt][nt], a[mt], b[nt][0], b[nt][1]);
        }
    }

    // epilogue: direct to out
#pragma unroll
    for (int mt = 0; mt < 2; mt++) {
#pragma unroll
        for (int h = 0; h < 2; h++) {
            int ml = wm + mt * 16 + (lane >> 2) + h * 8;
            int r = m0 + ml;
            if (r < rows) {
                int tok = sTok[ml];
                float w = sW[ml];
                float* drow = out + (size_t)tok * HDIM;
#pragma unroll
                for (int nt = 0; nt < 8; nt++) {
                    int col = n0 + wn + nt * 8 + 2 * (lane & 3);
                    float v0 = acc[mt][nt][h * 2 + 0];
                    float v1 = acc[mt][nt][h * 2 + 1];
                    if (shared_mode) {
                        *(float2*)(drow + col) = make_float2(v0, v1);
                    } else {
                        atomicAdd(drow + col + 0, w * v0);
                        atomicAdd(drow + col + 1, w * v1);
                    }
                }
            }
        }
    }
}

// ---------------- launch ----------------
extern "C" void kernel_launch(void* const* d_in, const int* in_sizes, int n_in,
                              void* d_out, int out_size) {
    (void)in_sizes; (void)n_in; (void)out_size;
    const float* x    = (const float*)d_in[0];
    const float* Wg_s = (const float*)d_in[1];
    const float* Wu_s = (const float*)d_in[2];
    const float* Wd_s = (const float*)d_in[3];
    const float* Wg   = (const float*)d_in[4];
    const float* Wu   = (const float*)d_in[5];
    const float* Wd   = (const float*)d_in[6];
    const float* Wr   = (const float*)d_in[7];
    const float* rb   = (const float*)d_in[8];
    float* out = (float*)d_out;

    cudaFuncSetAttribute(gateup_kernel, cudaFuncAttributeMaxDynamicSharedMemorySize, SMEM_BYTES);
    cudaFuncSetAttribute(down_kernel,   cudaFuncAttributeMaxDynamicSharedMemorySize, SMEM_BYTES);

    cvt_w_kernel<<<27648, 256>>>(Wg_s, Wu_s, Wd_s, Wg, Wu, Wd);     // launch 1 (also zeroes g_cnt)
    router_kernel<<<TOKS / 8, 256>>>(x, Wr, rb);                    // launch 2 (also writes g_xh)
    offs_kernel<<<1, 32>>>();                                       // launch 3
    gateup_kernel<<<dim3(IDIM / 64, TOKS / 256, NE + 1), 512, SMEM_BYTES>>>();   // launch 4
    down_kernel<<<dim3(HDIM / 128, TOKS / 256, 1), 512, SMEM_BYTES>>>(out, 1);   // launch 5
    down_kernel<<<dim3(HDIM / 128, TOKS / 256, NE), 512, SMEM_BYTES>>>(out, 0);  // launch 6 (profiled at -s 5)
}